// round 11
// baseline (speedup 1.0000x reference)
#include <cuda_runtime.h>
#include <cstdint>
#include <cstddef>

// LSTM T=512 B=64 I=H=512 fp32.
// K1: transpose x -> g_xT[t][i][b]
// K2: xproj GEMM -> g_xproj[t][g][b] (+both biases), 8x8 register tiles, conflict-free LDS
// K3: persistent recurrence, 128 blocks x 256 thr, 16 half-warp k-covers, conflict-free LDS

#define TT 512
#define BB 64
#define HH 512
#define GG 2048

typedef unsigned long long ull;

__device__ float    g_xT[(size_t)TT * HH * BB];
__device__ float    g_xproj[(size_t)TT * GG * BB];
__device__ float    g_hbuf[2][HH * BB];
__device__ unsigned g_flags[128];

// ---------------- helpers ----------------
__device__ __forceinline__ ull fma2(ull a, ull b, ull c) {
    ull d; asm("fma.rn.f32x2 %0, %1, %2, %3;" : "=l"(d) : "l"(a), "l"(b), "l"(c)); return d;
}
__device__ __forceinline__ ull pack2(float x, float y) {
    ull d; asm("mov.b64 %0, {%1, %2};" : "=l"(d) : "f"(x), "f"(y)); return d;
}
__device__ __forceinline__ float2 unpack2(ull v) {
    float2 r; asm("mov.b64 {%0, %1}, %2;" : "=f"(r.x), "=f"(r.y) : "l"(v)); return r;
}
__device__ __forceinline__ unsigned ld_acq(const unsigned* p) {
    unsigned v; asm volatile("ld.global.acquire.gpu.u32 %0, [%1];" : "=r"(v) : "l"(p)); return v;
}
__device__ __forceinline__ void st_rel(unsigned* p, unsigned v) {
    asm volatile("st.global.release.gpu.u32 [%0], %1;" :: "l"(p), "r"(v));
}
__device__ __forceinline__ float sigm(float x) { return 1.0f / (1.0f + __expf(-x)); }

__device__ __forceinline__ void cp_async16(uint32_t smem_addr, const void* gptr) {
    asm volatile("cp.async.cg.shared.global [%0], [%1], 16;" :: "r"(smem_addr), "l"(gptr));
}
#define CP_COMMIT() asm volatile("cp.async.commit_group;" ::: "memory")
#define CP_WAIT(n)  asm volatile("cp.async.wait_group " #n ";" ::: "memory")

// 8-row FMA: duplicated w into 4 batch-pair accumulators (uses locals x0,x1,a)
#define ROWF(i, wv) { ull wd = pack2(wv, wv); \
    a[i][0] = fma2(x0.x, wd, a[i][0]); a[i][1] = fma2(x0.y, wd, a[i][1]); \
    a[i][2] = fma2(x1.x, wd, a[i][2]); a[i][3] = fma2(x1.y, wd, a[i][3]); }

// ---------------- K1: x transpose to [t][i][b] ----------------
__global__ void __launch_bounds__(256) xT_kernel(const float* __restrict__ x)
{
    __shared__ float ts[64][65];
    const int t  = blockIdx.y;
    const int i0 = blockIdx.x * 64;
    const int tid = threadIdx.x;
#pragma unroll
    for (int p = 0; p < 16; ++p) {
        int lin = p * 256 + tid;
        int b = lin >> 6, i = lin & 63;
        ts[i][b] = x[((size_t)t * BB + b) * HH + i0 + i];
    }
    __syncthreads();
#pragma unroll
    for (int p = 0; p < 16; ++p) {
        int lin = p * 256 + tid;
        int i = lin >> 6, b = lin & 63;
        g_xT[((size_t)t * HH + i0 + i) * BB + b] = ts[i][b];
    }
}

// ---------------- K2: xproj GEMM ----------------
// Block: 256 g x 64 b at one t. Per-thread 8g x 8b.
// g rows: 4 consecutive at g4=(tid&31)*4 plus 4 at g4+128  -> conflict-free LDS.128.
// b cols: b8=(tid>>5)*8 (warp-uniform -> broadcast).
__global__ void __launch_bounds__(256) xproj_kernel(
    const float* __restrict__ Wih,
    const float* __restrict__ bih,
    const float* __restrict__ bhh)
{
    __shared__ float Wst[16 * 256];   // [k][g] 16KB
    __shared__ float Xst[16 * 64];    // [k][b] 4KB

    const int t   = blockIdx.y;
    const int g0  = blockIdx.x * 256;
    const int tid = threadIdx.x;
    const int g4  = (tid & 31) * 4;
    const int b8  = (tid >> 5) * 8;

    const float*  wsrc = Wih + (size_t)(g0 + tid) * HH;
    const float4* xsrc = (const float4*)(g_xT + (size_t)t * (HH * BB));

    float4 wpre[4];
#pragma unroll
    for (int q = 0; q < 4; ++q) wpre[q] = *(const float4*)(wsrc + q * 4);
    float4 xpre = __ldcs(xsrc + tid);

    ull a[8][4];
#pragma unroll
    for (int i = 0; i < 8; ++i)
#pragma unroll
        for (int j = 0; j < 4; ++j) a[i][j] = 0ull;

    for (int s = 0; s < 32; ++s) {
#pragma unroll
        for (int q = 0; q < 4; ++q) {
            Wst[(q * 4 + 0) * 256 + tid] = wpre[q].x;
            Wst[(q * 4 + 1) * 256 + tid] = wpre[q].y;
            Wst[(q * 4 + 2) * 256 + tid] = wpre[q].z;
            Wst[(q * 4 + 3) * 256 + tid] = wpre[q].w;
        }
        ((float4*)Xst)[tid] = xpre;
        __syncthreads();
        if (s < 31) {
#pragma unroll
            for (int q = 0; q < 4; ++q)
                wpre[q] = *(const float4*)(wsrc + (s + 1) * 16 + q * 4);
            xpre = __ldcs(xsrc + (s + 1) * 256 + tid);
        }
#pragma unroll
        for (int k = 0; k < 16; ++k) {
            float4 w0 = *(const float4*)&Wst[k * 256 + g4];          // rows g4..g4+3
            float4 w1 = *(const float4*)&Wst[k * 256 + 128 + g4];    // rows g4+128..+131
            ulonglong2 x0 = *(const ulonglong2*)&Xst[k * 64 + b8];
            ulonglong2 x1 = *(const ulonglong2*)&Xst[k * 64 + b8 + 4];
            ROWF(0, w0.x) ROWF(1, w0.y) ROWF(2, w0.z) ROWF(3, w0.w)
            ROWF(4, w1.x) ROWF(5, w1.y) ROWF(6, w1.z) ROWF(7, w1.w)
        }
        __syncthreads();
    }

#pragma unroll
    for (int i = 0; i < 8; ++i) {
        int g = g0 + (i < 4 ? g4 + i : 128 + g4 + (i - 4));
        float bi = bih[g] + bhh[g];
        float2 v0 = unpack2(a[i][0]), v1 = unpack2(a[i][1]);
        float2 v2 = unpack2(a[i][2]), v3 = unpack2(a[i][3]);
        float* dst = g_xproj + ((size_t)t * GG + g) * BB + b8;
        *(float4*)dst       = make_float4(v0.x + bi, v0.y + bi, v1.x + bi, v1.y + bi);
        *(float4*)(dst + 4) = make_float4(v2.x + bi, v2.y + bi, v3.x + bi, v3.y + bi);
    }
}

// ---------------- K3: persistent recurrence ----------------
// SMEM floats: Wt[512][16]=8192 (32KB) | hs[512][64]=32768 (128KB) | hout 256
#define SMO_HS   8192
#define SMO_HOUT 40960
#define SM_FLOATS 41216

__global__ void __launch_bounds__(256, 1) lstm_rec_kernel(
    const float* __restrict__ Whh,
    float* __restrict__ out)
{
    extern __shared__ float sm[];
    float* Wt   = sm;                 // [k][r] 16 gate-rows
    float* hs   = sm + SMO_HS;        // [k][b]; cover kc owns [kc*32..+32)
    float* hout = sm + SMO_HOUT;

    const int tid = threadIdx.x;
    const int bid = blockIdx.x;
    const int j0  = bid * 4;

    // compute mapping: 16 covers x (2 row-groups x 8 batch-groups)
    const int kc    = tid >> 4;          // k-cover: k in [kc*32, kc*32+32)
    const int rg    = (tid >> 3) & 1;    // rows rg*8..rg*8+7
    const int b4    = (tid & 7) * 4;     // batches b4..b4+3 and b4+32..b4+35
    const int lid16 = tid & 15;
    const unsigned halfmask = (tid & 16) ? 0xFFFF0000u : 0x0000FFFFu;

    // epilogue mapping
    const int jj = tid >> 6;             // 0..3
    const int be = tid & 63;

    // ---- load W slice transposed: Wt[k][r], r = q*4+jj' ----
    {
        int r = tid >> 4, seg = tid & 15;
        int grow = (r >> 2) * HH + j0 + (r & 3);
        const float* src = Whh + (size_t)grow * HH + seg * 32;
#pragma unroll
        for (int q = 0; q < 32; q += 4) {
            float4 v = *(const float4*)(src + q);
            int k = seg * 32 + q;
            Wt[(k + 0) * 16 + r] = v.x;
            Wt[(k + 1) * 16 + r] = v.y;
            Wt[(k + 2) * 16 + r] = v.z;
            Wt[(k + 3) * 16 + r] = v.w;
        }
    }

    __shared__ unsigned s_base;
    if (tid == 0) s_base = ld_acq(&g_flags[bid]);
    __syncthreads();
    const unsigned base = s_base;

    float c_reg = 0.0f;

    const uint32_t hs_sm = (uint32_t)__cvta_generic_to_shared(hs + kc * 2048);
    const float* wbase = Wt + rg * 8;
    const float* hbase = hs + kc * 2048 + b4;

    for (int t = 0; t < TT; ++t) {
        // prefetch x_proj for epilogue (independent of flags)
        const float* xpt = g_xproj + (size_t)t * (GG * BB) + (size_t)(j0 + jj) * BB + be;
        float xp0 = __ldcs(xpt);
        float xp1 = __ldcs(xpt + (size_t)HH * BB);
        float xp2 = __ldcs(xpt + (size_t)2 * HH * BB);
        float xp3 = __ldcs(xpt + (size_t)3 * HH * BB);

        if (t > 0) {
            // flag barrier: wait for all blocks to publish h(t-1)
            if (tid < 32) {
                unsigned tgt = base + (unsigned)t;
                for (;;) {
                    unsigned v0 = ld_acq(&g_flags[tid]);
                    unsigned v1 = ld_acq(&g_flags[tid + 32]);
                    unsigned v2 = ld_acq(&g_flags[tid + 64]);
                    unsigned v3 = ld_acq(&g_flags[tid + 96]);
                    bool ok = ((int)(v0 - tgt) >= 0) & ((int)(v1 - tgt) >= 0) &
                              ((int)(v2 - tgt) >= 0) & ((int)(v3 - tgt) >= 0);
                    if (__all_sync(0xffffffffu, ok)) break;
                    __nanosleep(32);
                }
            }
            __syncthreads();

            // cover kc stages its own 8KB h slice via cp.async, 4 groups of 8 k
            const float4* hsrc = (const float4*)(g_hbuf[(t + 1) & 1]) + kc * 512;
#pragma unroll
            for (int c = 0; c < 4; ++c) {
#pragma unroll
                for (int jq = 0; jq < 8; ++jq) {
                    int idx = lid16 + (c * 8 + jq) * 16;
                    cp_async16(hs_sm + idx * 16, hsrc + idx);
                }
                CP_COMMIT();
            }

            ull a[8][4];
#pragma unroll
            for (int i = 0; i < 8; ++i)
#pragma unroll
                for (int j = 0; j < 4; ++j) a[i][j] = 0ull;

#define REC_CHUNK(c) { \
    __syncwarp(halfmask); \
    _Pragma("unroll") \
    for (int kk = c * 8; kk < c * 8 + 8; ++kk) { \
        int k = kc * 32 + kk; \
        float4 w0 = *(const float4*)(wbase + k * 16); \
        float4 w1 = *(const float4*)(wbase + k * 16 + 4); \
        ulonglong2 x0 = *(const ulonglong2*)(hbase + kk * 64); \
        ulonglong2 x1 = *(const ulonglong2*)(hbase + kk * 64 + 32); \
        ROWF(0, w0.x) ROWF(1, w0.y) ROWF(2, w0.z) ROWF(3, w0.w) \
        ROWF(4, w1.x) ROWF(5, w1.y) ROWF(6, w1.z) ROWF(7, w1.w) \
    } }

            CP_WAIT(3); REC_CHUNK(0)
            CP_WAIT(2); REC_CHUNK(1)
            CP_WAIT(1); REC_CHUNK(2)
            CP_WAIT(0); REC_CHUNK(3)
#undef REC_CHUNK

            // write partials into own (now dead) h slice: ps[r][b] at hs[kc*2048]
            float* ps = hs + kc * 2048;
#pragma unroll
            for (int i = 0; i < 8; ++i) {
                float2 v0 = unpack2(a[i][0]), v1 = unpack2(a[i][1]);
                float2 v2 = unpack2(a[i][2]), v3 = unpack2(a[i][3]);
                float* row = ps + (rg * 8 + i) * 64 + b4;
                *(float4*)row        = make_float4(v0.x, v0.y, v1.x, v1.y);
                *(float4*)(row + 32) = make_float4(v2.x, v2.y, v3.x, v3.y);
            }
        }
        __syncthreads();

        // ---- reduce 16 covers + gate math; thread owns (jj, be) ----
        float gi = xp0, gf = xp1, gg = xp2, go = xp3;
        if (t > 0) {
#pragma unroll
            for (int k16 = 0; k16 < 16; ++k16) {
                const float* ps = hs + k16 * 2048;
                gi += ps[(0 * 4 + jj) * 64 + be];
                gf += ps[(1 * 4 + jj) * 64 + be];
                gg += ps[(2 * 4 + jj) * 64 + be];
                go += ps[(3 * 4 + jj) * 64 + be];
            }
        }
        float iv = sigm(gi);
        float fv = sigm(gf);
        float gv = tanhf(gg);
        float ov = sigm(go);
        c_reg = fv * c_reg + iv * gv;
        float h = ov * tanhf(c_reg);
        __stcg(&g_hbuf[t & 1][(j0 + jj) * 64 + be], h);
        hout[jj * 64 + be] = h;

        __syncthreads();
        if (tid == 0) st_rel(&g_flags[bid], base + (unsigned)t + 1u);

        // coalesced out write: thread b writes float4 [t][b][j0..j0+3]
        if (tid < 64) {
            float4 hv = make_float4(hout[tid], hout[64 + tid], hout[128 + tid], hout[192 + tid]);
            *(float4*)&out[((size_t)t * BB + tid) * HH + j0] = hv;
        }
    }
}

// ---------------- launch ----------------
extern "C" void kernel_launch(void* const* d_in, const int* in_sizes, int n_in,
                              void* d_out, int out_size)
{
    const float* x   = (const float*)d_in[0];
    const float* Wih = (const float*)d_in[1];
    const float* Whh = (const float*)d_in[2];
    const float* bih = (const float*)d_in[3];
    const float* bhh = (const float*)d_in[4];
    float* out = (float*)d_out;

    dim3 gT(HH / 64, TT);
    xT_kernel<<<gT, 256>>>(x);

    dim3 gP(GG / 256, TT);
    xproj_kernel<<<gP, 256>>>(Wih, bih, bhh);

    size_t smem = (size_t)SM_FLOATS * sizeof(float);
    cudaFuncSetAttribute(lstm_rec_kernel,
                         cudaFuncAttributeMaxDynamicSharedMemorySize, (int)smem);
    lstm_rec_kernel<<<128, 256, smem>>>(Whh, out);
}

// round 13
// speedup vs baseline: 1.1027x; 1.1027x over previous
#include <cuda_runtime.h>
#include <cstdint>
#include <cstddef>

// LSTM T=512 B=64 I=H=512 fp32.
// K1: transpose x -> g_xT[t][i][b]
// K2: xproj GEMM -> g_xproj[t][g][b] (+both biases), 8x8 register tiles
// K3: persistent recurrence, 128 blocks x 512 thr, 32 half-warp k-covers (16 k each)

#define TT 512
#define BB 64
#define HH 512
#define GG 2048

typedef unsigned long long ull;

__device__ float    g_xT[(size_t)TT * HH * BB];
__device__ float    g_xproj[(size_t)TT * GG * BB];
__device__ float    g_hbuf[2][HH * BB];
__device__ unsigned g_flags[128];

// ---------------- helpers ----------------
__device__ __forceinline__ ull fma2(ull a, ull b, ull c) {
    ull d; asm("fma.rn.f32x2 %0, %1, %2, %3;" : "=l"(d) : "l"(a), "l"(b), "l"(c)); return d;
}
__device__ __forceinline__ ull pack2(float x, float y) {
    ull d; asm("mov.b64 %0, {%1, %2};" : "=l"(d) : "f"(x), "f"(y)); return d;
}
__device__ __forceinline__ float2 unpack2(ull v) {
    float2 r; asm("mov.b64 {%0, %1}, %2;" : "=f"(r.x), "=f"(r.y) : "l"(v)); return r;
}
__device__ __forceinline__ unsigned ld_acq(const unsigned* p) {
    unsigned v; asm volatile("ld.global.acquire.gpu.u32 %0, [%1];" : "=r"(v) : "l"(p)); return v;
}
__device__ __forceinline__ void st_rel(unsigned* p, unsigned v) {
    asm volatile("st.global.release.gpu.u32 [%0], %1;" :: "l"(p), "r"(v));
}
__device__ __forceinline__ float sigm(float x) { return 1.0f / (1.0f + __expf(-x)); }

__device__ __forceinline__ void cp_async16(uint32_t smem_addr, const void* gptr) {
    asm volatile("cp.async.cg.shared.global [%0], [%1], 16;" :: "r"(smem_addr), "l"(gptr));
}
#define CP_COMMIT() asm volatile("cp.async.commit_group;" ::: "memory")
#define CP_WAIT(n)  asm volatile("cp.async.wait_group " #n ";" ::: "memory")

// 8-row FMA: duplicated w into 4 batch-pair accumulators (uses locals x0,x1,a)
#define ROWF(i, wv) { ull wd = pack2(wv, wv); \
    a[i][0] = fma2(x0.x, wd, a[i][0]); a[i][1] = fma2(x0.y, wd, a[i][1]); \
    a[i][2] = fma2(x1.x, wd, a[i][2]); a[i][3] = fma2(x1.y, wd, a[i][3]); }

// ---------------- K1: x transpose to [t][i][b] ----------------
__global__ void __launch_bounds__(256) xT_kernel(const float* __restrict__ x)
{
    __shared__ float ts[64][65];
    const int t  = blockIdx.y;
    const int i0 = blockIdx.x * 64;
    const int tid = threadIdx.x;
#pragma unroll
    for (int p = 0; p < 16; ++p) {
        int lin = p * 256 + tid;
        int b = lin >> 6, i = lin & 63;
        ts[i][b] = x[((size_t)t * BB + b) * HH + i0 + i];
    }
    __syncthreads();
#pragma unroll
    for (int p = 0; p < 16; ++p) {
        int lin = p * 256 + tid;
        int i = lin >> 6, b = lin & 63;
        g_xT[((size_t)t * HH + i0 + i) * BB + b] = ts[i][b];
    }
}

// ---------------- K2: xproj GEMM ----------------
// Block: 256 g x 64 b at one t. Per-thread 8g x 8b.
__global__ void __launch_bounds__(256) xproj_kernel(
    const float* __restrict__ Wih,
    const float* __restrict__ bih,
    const float* __restrict__ bhh)
{
    __shared__ float Wst[16 * 256];   // [k][g] 16KB
    __shared__ float Xst[16 * 64];    // [k][b] 4KB

    const int t   = blockIdx.y;
    const int g0  = blockIdx.x * 256;
    const int tid = threadIdx.x;
    const int g4  = (tid & 31) * 4;
    const int b8  = (tid >> 5) * 8;

    const float*  wsrc = Wih + (size_t)(g0 + tid) * HH;
    const float4* xsrc = (const float4*)(g_xT + (size_t)t * (HH * BB));

    float4 wpre[4];
#pragma unroll
    for (int q = 0; q < 4; ++q) wpre[q] = *(const float4*)(wsrc + q * 4);
    float4 xpre = __ldcs(xsrc + tid);

    ull a[8][4];
#pragma unroll
    for (int i = 0; i < 8; ++i)
#pragma unroll
        for (int j = 0; j < 4; ++j) a[i][j] = 0ull;

    for (int s = 0; s < 32; ++s) {
#pragma unroll
        for (int q = 0; q < 4; ++q) {
            Wst[(q * 4 + 0) * 256 + tid] = wpre[q].x;
            Wst[(q * 4 + 1) * 256 + tid] = wpre[q].y;
            Wst[(q * 4 + 2) * 256 + tid] = wpre[q].z;
            Wst[(q * 4 + 3) * 256 + tid] = wpre[q].w;
        }
        ((float4*)Xst)[tid] = xpre;
        __syncthreads();
        if (s < 31) {
#pragma unroll
            for (int q = 0; q < 4; ++q)
                wpre[q] = *(const float4*)(wsrc + (s + 1) * 16 + q * 4);
            xpre = __ldcs(xsrc + (s + 1) * 256 + tid);
        }
#pragma unroll
        for (int k = 0; k < 16; ++k) {
            float4 w0 = *(const float4*)&Wst[k * 256 + g4];
            float4 w1 = *(const float4*)&Wst[k * 256 + 128 + g4];
            ulonglong2 x0 = *(const ulonglong2*)&Xst[k * 64 + b8];
            ulonglong2 x1 = *(const ulonglong2*)&Xst[k * 64 + b8 + 4];
            ROWF(0, w0.x) ROWF(1, w0.y) ROWF(2, w0.z) ROWF(3, w0.w)
            ROWF(4, w1.x) ROWF(5, w1.y) ROWF(6, w1.z) ROWF(7, w1.w)
        }
        __syncthreads();
    }

#pragma unroll
    for (int i = 0; i < 8; ++i) {
        int g = g0 + (i < 4 ? g4 + i : 128 + g4 + (i - 4));
        float bi = bih[g] + bhh[g];
        float2 v0 = unpack2(a[i][0]), v1 = unpack2(a[i][1]);
        float2 v2 = unpack2(a[i][2]), v3 = unpack2(a[i][3]);
        float* dst = g_xproj + ((size_t)t * GG + g) * BB + b8;
        *(float4*)dst       = make_float4(v0.x + bi, v0.y + bi, v1.x + bi, v1.y + bi);
        *(float4*)(dst + 4) = make_float4(v2.x + bi, v2.y + bi, v3.x + bi, v3.y + bi);
    }
}

// ---------------- K3: persistent recurrence (512 threads) ----------------
// SMEM floats: Wt[512][16]=8192 (32KB) | hs (32 covers x 1024)=32768 (128KB) | hout 256
#define SMO_HS   8192
#define SMO_HOUT 40960
#define SM_FLOATS 41216

__global__ void __launch_bounds__(512, 1) lstm_rec_kernel(
    const float* __restrict__ Whh,
    float* __restrict__ out)
{
    extern __shared__ float sm[];
    float* Wt   = sm;                 // [k][r], r = gate*4 + col
    float* hs   = sm + SMO_HS;        // cover kc owns floats [kc*1024, kc*1024+1024)
    float* hout = sm + SMO_HOUT;

    const int tid = threadIdx.x;
    const int bid = blockIdx.x;
    const int j0  = bid * 4;

    // compute mapping: 32 covers (half-warps), each 16 k x 16 r x 64 b
    const int kc    = tid >> 4;          // 0..31, k in [kc*16, kc*16+16)
    const int rg    = (tid >> 3) & 1;    // rows rg*8..rg*8+7
    const int b4    = (tid & 7) * 4;     // batches b4..b4+3 and b4+32..b4+35
    const int lid16 = tid & 15;
    const unsigned halfmask = (tid & 16) ? 0xFFFF0000u : 0x0000FFFFu;

    // epilogue owners: tid < 256, thread owns (col jj, batch be)
    const int jj = (tid >> 6) & 3;
    const int be = tid & 63;
    const bool owner = (tid < 256);

    // ---- load W slice transposed: Wt[k][r] ----
    {
        int r = tid >> 5, seg = tid & 31;   // r 0..15, seg 0..31 (16-k chunks)
        int grow = (r >> 2) * HH + j0 + (r & 3);
        const float* src = Whh + (size_t)grow * HH + seg * 16;
#pragma unroll
        for (int q = 0; q < 16; q += 4) {
            float4 v = *(const float4*)(src + q);
            int k = seg * 16 + q;
            Wt[(k + 0) * 16 + r] = v.x;
            Wt[(k + 1) * 16 + r] = v.y;
            Wt[(k + 2) * 16 + r] = v.z;
            Wt[(k + 3) * 16 + r] = v.w;
        }
    }

    __shared__ unsigned s_base;
    if (tid == 0) s_base = ld_acq(&g_flags[bid]);
    __syncthreads();
    const unsigned base = s_base;

    float c_reg = 0.0f;

    const uint32_t hs_sm = (uint32_t)__cvta_generic_to_shared(hs + kc * 1024);
    const float* wbase = Wt + rg * 8;
    const float* hbase = hs + kc * 1024 + b4;

    for (int t = 0; t < TT; ++t) {
        // prefetch x_proj for epilogue (independent of flags)
        float xp0 = 0.f, xp1 = 0.f, xp2 = 0.f, xp3 = 0.f;
        if (owner) {
            const float* xpt = g_xproj + (size_t)t * (GG * BB) + (size_t)(j0 + jj) * BB + be;
            xp0 = __ldcs(xpt);
            xp1 = __ldcs(xpt + (size_t)HH * BB);
            xp2 = __ldcs(xpt + (size_t)2 * HH * BB);
            xp3 = __ldcs(xpt + (size_t)3 * HH * BB);
        }

        if (t > 0) {
            // flag barrier: wait for all blocks to publish h(t-1)
            if (tid < 32) {
                unsigned tgt = base + (unsigned)t;
                for (;;) {
                    unsigned v0 = ld_acq(&g_flags[tid]);
                    unsigned v1 = ld_acq(&g_flags[tid + 32]);
                    unsigned v2 = ld_acq(&g_flags[tid + 64]);
                    unsigned v3 = ld_acq(&g_flags[tid + 96]);
                    bool ok = ((int)(v0 - tgt) >= 0) & ((int)(v1 - tgt) >= 0) &
                              ((int)(v2 - tgt) >= 0) & ((int)(v3 - tgt) >= 0);
                    if (__all_sync(0xffffffffu, ok)) break;
                    __nanosleep(32);
                }
            }
            __syncthreads();

            // cover kc stages its 4KB h slice (16 k x 64 b) via cp.async, 4 groups of 4 k
            const float4* hsrc = (const float4*)(g_hbuf[(t + 1) & 1]) + kc * 256;
#pragma unroll
            for (int c = 0; c < 4; ++c) {
#pragma unroll
                for (int jq = 0; jq < 4; ++jq) {
                    int idx = c * 64 + jq * 16 + lid16;
                    cp_async16(hs_sm + idx * 16, hsrc + idx);
                }
                CP_COMMIT();
            }

            ull a[8][4];
#pragma unroll
            for (int i = 0; i < 8; ++i)
#pragma unroll
                for (int j = 0; j < 4; ++j) a[i][j] = 0ull;

#define REC_CHUNK(c) { \
    __syncwarp(halfmask); \
    _Pragma("unroll") \
    for (int kk = c * 4; kk < c * 4 + 4; ++kk) { \
        int k = kc * 16 + kk; \
        float4 w0 = *(const float4*)(wbase + k * 16); \
        float4 w1 = *(const float4*)(wbase + k * 16 + 4); \
        ulonglong2 x0 = *(const ulonglong2*)(hbase + kk * 64); \
        ulonglong2 x1 = *(const ulonglong2*)(hbase + kk * 64 + 32); \
        ROWF(0, w0.x) ROWF(1, w0.y) ROWF(2, w0.z) ROWF(3, w0.w) \
        ROWF(4, w1.x) ROWF(5, w1.y) ROWF(6, w1.z) ROWF(7, w1.w) \
    } }

            CP_WAIT(3); REC_CHUNK(0)
            CP_WAIT(2); REC_CHUNK(1)
            CP_WAIT(1); REC_CHUNK(2)
            CP_WAIT(0); REC_CHUNK(3)
#undef REC_CHUNK

            // write partials into own (now dead) slice: ps[r][b]
            float* ps = hs + kc * 1024;
#pragma unroll
            for (int i = 0; i < 8; ++i) {
                float2 v0 = unpack2(a[i][0]), v1 = unpack2(a[i][1]);
                float2 v2 = unpack2(a[i][2]), v3 = unpack2(a[i][3]);
                float* row = ps + (rg * 8 + i) * 64 + b4;
                *(float4*)row        = make_float4(v0.x, v0.y, v1.x, v1.y);
                *(float4*)(row + 32) = make_float4(v2.x, v2.y, v3.x, v3.y);
            }
        }
        __syncthreads();

        // ---- owners reduce 32 covers + gate math ----
        if (owner) {
            float gi = xp0, gf = xp1, gg = xp2, go = xp3;
            if (t > 0) {
#pragma unroll
                for (int k32 = 0; k32 < 32; ++k32) {
                    const float* ps = hs + k32 * 1024;
                    gi += ps[(0 * 4 + jj) * 64 + be];
                    gf += ps[(1 * 4 + jj) * 64 + be];
                    gg += ps[(2 * 4 + jj) * 64 + be];
                    go += ps[(3 * 4 + jj) * 64 + be];
                }
            }
            float iv = sigm(gi);
            float fv = sigm(gf);
            float gv = tanhf(gg);
            float ov = sigm(go);
            c_reg = fv * c_reg + iv * gv;
            float h = ov * tanhf(c_reg);
            __stcg(&g_hbuf[t & 1][(j0 + jj) * 64 + be], h);
            hout[jj * 64 + be] = h;
        }

        __syncthreads();
        if (tid == 0) st_rel(&g_flags[bid], base + (unsigned)t + 1u);

        // coalesced out write: thread b writes float4 [t][b][j0..j0+3]
        if (tid < 64) {
            float4 hv = make_float4(hout[tid], hout[64 + tid], hout[128 + tid], hout[192 + tid]);
            *(float4*)&out[((size_t)t * BB + tid) * HH + j0] = hv;
        }
    }
}

// ---------------- launch ----------------
extern "C" void kernel_launch(void* const* d_in, const int* in_sizes, int n_in,
                              void* d_out, int out_size)
{
    const float* x   = (const float*)d_in[0];
    const float* Wih = (const float*)d_in[1];
    const float* Whh = (const float*)d_in[2];
    const float* bih = (const float*)d_in[3];
    const float* bhh = (const float*)d_in[4];
    float* out = (float*)d_out;

    dim3 gT(HH / 64, TT);
    xT_kernel<<<gT, 256>>>(x);

    dim3 gP(GG / 256, TT);
    xproj_kernel<<<gP, 256>>>(Wih, bih, bhh);

    size_t smem = (size_t)SM_FLOATS * sizeof(float);
    cudaFuncSetAttribute(lstm_rec_kernel,
                         cudaFuncAttributeMaxDynamicSharedMemorySize, (int)smem);
    lstm_rec_kernel<<<128, 512, smem>>>(Whh, out);
}